// round 1
// baseline (speedup 1.0000x reference)
#include <cuda_runtime.h>
#include <cstdint>

// Problem constants
#define B_TOT   8192
#define NF      32
#define D       64
#define NIX     496      // 32*31/2
#define BT      128      // batch tile per CTA
#define NTHREADS 256
#define P_PAD   68       // padded row length (floats) for bank-conflict-free access

// cp.async 16B global->shared
__device__ __forceinline__ void cp16(float* dst, const float* src) {
    uint32_t d = (uint32_t)__cvta_generic_to_shared(dst);
    asm volatile("cp.async.cg.shared.global [%0], [%1], 16;\n" :: "r"(d), "l"(src));
}

// Dynamic smem layout (floats):
//   sP   [BT][P_PAD]   p tile  (x[:, row(n), :])
//   sQ   [BT][P_PAD]   q tile  (x[:, col(n), :])
//   sKr  [64][P_PAD]   K rows as stored   (K[o][i])
//   sKT  [64][P_PAD]   K transposed       (KT[i][o])
#define SMEM_FLOATS (2 * BT * P_PAD + 2 * 64 * P_PAD)

extern "C" __global__ void __launch_bounds__(NTHREADS, 2)
opn_kernel(const float* __restrict__ x,
           const float* __restrict__ kern,
           float* __restrict__ out)
{
    const int n    = blockIdx.x;      // pair index 0..495
    const int bblk = blockIdx.y;      // batch block 0..63
    const int tid  = threadIdx.x;

    // Decode triu pair (row r, col c) from n  (np.triu_indices(NF, k=1) order)
    int r = 0, nn = n;
    while (nn >= (NF - 1 - r)) { nn -= (NF - 1 - r); r++; }
    const int c = r + 1 + nn;

    extern __shared__ float smem[];
    float* sP  = smem;
    float* sQ  = sP  + BT * P_PAD;
    float* sKr = sQ  + BT * P_PAD;
    float* sKT = sKr + 64 * P_PAD;

    const int b0 = bblk * BT;

    // ---------------- async tile loads ----------------
    {
        const int f4   = tid & 15;    // float4 index within a 64-float row
        const int rrow = tid >> 4;    // 16 rows per pass

        const float* xp = x + ((size_t)b0 * NF + r) * D;
        const float* xq = x + ((size_t)b0 * NF + c) * D;
        #pragma unroll
        for (int pass = 0; pass < BT / 16; ++pass) {
            int b = rrow + pass * 16;
            const size_t go = (size_t)b * NF * D + f4 * 4;
            cp16(&sP[b * P_PAD + f4 * 4], xp + go);
            cp16(&sQ[b * P_PAD + f4 * 4], xq + go);
        }
        // K rows: K[o][i] = kern[o*NIX*D + n*D + i]
        const float* kp = kern + (size_t)n * D;
        #pragma unroll
        for (int pass = 0; pass < 4; ++pass) {
            int o = rrow + pass * 16;
            cp16(&sKr[o * P_PAD + f4 * 4], kp + (size_t)o * NIX * D + f4 * 4);
        }
    }
    asm volatile("cp.async.commit_group;\n" ::: "memory");
    asm volatile("cp.async.wait_group 0;\n" ::: "memory");
    __syncthreads();

    // ---------------- transpose K in smem: sKT[i][o] = sKr[o][i] ----------------
    {
        const int o   = tid >> 2;          // 0..63
        const int i4b = tid & 3;
        #pragma unroll
        for (int rr = 0; rr < 4; ++rr) {
            int i4 = i4b + 4 * rr;         // 0..15
            float4 v = *(const float4*)&sKr[o * P_PAD + i4 * 4];
            sKT[(i4 * 4 + 0) * P_PAD + o] = v.x;
            sKT[(i4 * 4 + 1) * P_PAD + o] = v.y;
            sKT[(i4 * 4 + 2) * P_PAD + o] = v.z;
            sKT[(i4 * 4 + 3) * P_PAD + o] = v.w;
        }
    }
    __syncthreads();

    // ---------------- main loop: t[b][o] = sum_i p[b][i] * K[o][i] ----------------
    // Thread owns b in {bbg, bbg+32, bbg+64, bbg+96}, o in {ob*4..+3} u {32+ob*4..+3}
    const int ob  = tid & 7;    // 0..7
    const int bbg = tid >> 3;   // 0..31

    float acc[4][8];
    #pragma unroll
    for (int v = 0; v < 4; ++v)
        #pragma unroll
        for (int u = 0; u < 8; ++u) acc[v][u] = 0.0f;

    #pragma unroll 4
    for (int i4 = 0; i4 < 16; ++i4) {
        float4 pv[4];
        #pragma unroll
        for (int v = 0; v < 4; ++v)
            pv[v] = *(const float4*)&sP[(bbg + 32 * v) * P_PAD + i4 * 4];

        #pragma unroll
        for (int d = 0; d < 4; ++d) {
            const int i = i4 * 4 + d;
            float4 k0 = *(const float4*)&sKT[i * P_PAD + ob * 4];
            float4 k1 = *(const float4*)&sKT[i * P_PAD + 32 + ob * 4];
            #pragma unroll
            for (int v = 0; v < 4; ++v) {
                float pd = (d == 0) ? pv[v].x : (d == 1) ? pv[v].y : (d == 2) ? pv[v].z : pv[v].w;
                acc[v][0] = fmaf(pd, k0.x, acc[v][0]);
                acc[v][1] = fmaf(pd, k0.y, acc[v][1]);
                acc[v][2] = fmaf(pd, k0.z, acc[v][2]);
                acc[v][3] = fmaf(pd, k0.w, acc[v][3]);
                acc[v][4] = fmaf(pd, k1.x, acc[v][4]);
                acc[v][5] = fmaf(pd, k1.y, acc[v][5]);
                acc[v][6] = fmaf(pd, k1.z, acc[v][6]);
                acc[v][7] = fmaf(pd, k1.w, acc[v][7]);
            }
        }
    }

    // ---------------- epilogue: out[b] = sum_o t[b][o] * q[b][o] ----------------
    #pragma unroll
    for (int v = 0; v < 4; ++v) {
        const int b = bbg + 32 * v;
        float4 q0 = *(const float4*)&sQ[b * P_PAD + ob * 4];
        float4 q1 = *(const float4*)&sQ[b * P_PAD + 32 + ob * 4];
        float s = acc[v][0] * q0.x + acc[v][1] * q0.y + acc[v][2] * q0.z + acc[v][3] * q0.w
                + acc[v][4] * q1.x + acc[v][5] * q1.y + acc[v][6] * q1.z + acc[v][7] * q1.w;
        // reduce across the 8-lane o-group (lanes ob=0..7 are contiguous)
        s += __shfl_down_sync(0xFFFFFFFFu, s, 4, 8);
        s += __shfl_down_sync(0xFFFFFFFFu, s, 2, 8);
        s += __shfl_down_sync(0xFFFFFFFFu, s, 1, 8);
        if (ob == 0)
            out[(size_t)(b0 + b) * NIX + n] = s;
    }
}

extern "C" void kernel_launch(void* const* d_in, const int* in_sizes, int n_in,
                              void* d_out, int out_size)
{
    (void)in_sizes; (void)n_in; (void)out_size;
    const float* x    = (const float*)d_in[0];   // (8192, 32, 64) f32
    const float* kern = (const float*)d_in[1];   // (64, 496, 64) f32
    float* out        = (float*)d_out;           // (8192, 496) f32

    const int smem_bytes = SMEM_FLOATS * (int)sizeof(float);   // 104448
    // Idempotent, cheap, legal during capture (not a stream/memory op).
    cudaFuncSetAttribute(opn_kernel, cudaFuncAttributeMaxDynamicSharedMemorySize, smem_bytes);

    dim3 grid(NIX, B_TOT / BT);   // (496, 64)
    opn_kernel<<<grid, NTHREADS, smem_bytes>>>(x, kern, out);
}

// round 3
// speedup vs baseline: 2.0748x; 2.0748x over previous
#include <cuda_runtime.h>
#include <cstdint>

#define B_TOT   8192
#define NF      32
#define D       64
#define NIX     496
#define BT      128
#define NTHREADS 256
#define STRIDE  68        // padded row stride (floats), conflict-free

// smem (floats): sP[128][68], sK[64][68], sQ[128][68]
#define SP_F (BT * STRIDE)
#define SK_F (64 * STRIDE)
#define SQ_F (BT * STRIDE)
#define SMEM_FLOATS (SP_F + SK_F + SQ_F)

__device__ __forceinline__ uint32_t smem_u32(const void* p) {
    uint32_t a;
    asm("{ .reg .u64 t; cvta.to.shared.u64 t, %1; cvt.u32.u64 %0, t; }" : "=r"(a) : "l"(p));
    return a;
}
__device__ __forceinline__ float f2tf32(float f) {
    uint32_t r; asm("cvt.rn.tf32.f32 %0, %1;" : "=r"(r) : "f"(f));
    return __uint_as_float(r);
}
__device__ __forceinline__ void cp16(void* dst, const float* src) {
    uint32_t d = smem_u32(dst);
    asm volatile("cp.async.cg.shared.global [%0], [%1], 16;\n" :: "r"(d), "l"(src));
}
__device__ __forceinline__ void mma_tf32(float d[4], const uint32_t a[4], const uint32_t b[2]) {
    asm volatile(
        "mma.sync.aligned.m16n8k8.row.col.f32.tf32.tf32.f32 "
        "{%0,%1,%2,%3}, {%4,%5,%6,%7}, {%8,%9}, {%0,%1,%2,%3};"
        : "+f"(d[0]), "+f"(d[1]), "+f"(d[2]), "+f"(d[3])
        : "r"(a[0]), "r"(a[1]), "r"(a[2]), "r"(a[3]), "r"(b[0]), "r"(b[1]));
}

extern "C" __global__ void __launch_bounds__(NTHREADS, 2)
opn_mma_kernel(const float* __restrict__ x,
               const float* __restrict__ kern,
               float* __restrict__ out)
{
    const int n    = blockIdx.x;
    const int bblk = blockIdx.y;
    const int tid  = threadIdx.x;
    const int wid  = tid >> 5;
    const int lane = tid & 31;
    const int b0   = bblk * BT;

    // decode triu pair (r, c)
    int r = 0, nn = n;
    while (nn >= (NF - 1 - r)) { nn -= (NF - 1 - r); r++; }
    const int c = r + 1 + nn;

    extern __shared__ float smem[];
    float* sP = smem;
    float* sK = sP + SP_F;
    float* sQ = sK + SK_F;

    // ---------------- loads ----------------
    {
        const int f4 = tid & 15;     // 16B chunk within 64-float row
        const int rb = tid >> 4;     // 0..15

        // P tile: x[:, r, :], tf32-rounded
        const float4* xp4 = (const float4*)(x + ((size_t)b0 * NF + r) * D);
        #pragma unroll
        for (int pass = 0; pass < 8; ++pass) {
            int b = rb + pass * 16;
            float4 v = __ldg(xp4 + (size_t)b * (NF * D / 4) + f4);
            float4 t = { f2tf32(v.x), f2tf32(v.y), f2tf32(v.z), f2tf32(v.w) };
            *(float4*)&sP[b * STRIDE + f4 * 4] = t;
        }
        // K tile: kern[o, n, :], tf32-rounded
        #pragma unroll
        for (int pass = 0; pass < 4; ++pass) {
            int o = rb + pass * 16;
            const float4* kp4 = (const float4*)(kern + ((size_t)o * NIX + n) * D);
            float4 v = __ldg(kp4 + f4);
            float4 t = { f2tf32(v.x), f2tf32(v.y), f2tf32(v.z), f2tf32(v.w) };
            *(float4*)&sK[o * STRIDE + f4 * 4] = t;
        }
        // Q tile: x[:, c, :], exact fp32, async
        const float* xq = x + ((size_t)b0 * NF + c) * D;
        #pragma unroll
        for (int pass = 0; pass < 8; ++pass) {
            int b = rb + pass * 16;
            cp16(&sQ[b * STRIDE + f4 * 4], xq + (size_t)b * NF * D + f4 * 4);
        }
    }
    asm volatile("cp.async.commit_group;\n" ::: "memory");
    asm volatile("cp.async.wait_group 0;\n" ::: "memory");
    __syncthreads();

    // ---------------- MMA main loop ----------------
    // Warp wm owns M rows [wm*16, wm*16+16); full N=64 (8 n-tiles), K=64 (8 k-steps).
    const int g    = lane >> 2;   // 0..7
    const int tig  = lane & 3;    // 0..3
    const int rowA = wid * 16;

    float acc[8][4];
    #pragma unroll
    for (int t = 0; t < 8; ++t)
        #pragma unroll
        for (int j = 0; j < 4; ++j) acc[t][j] = 0.0f;

    #pragma unroll
    for (int ks = 0; ks < 8; ++ks) {
        const int k0 = ks * 8;
        uint32_t a[4];
        a[0] = __float_as_uint(sP[(rowA + g)     * STRIDE + k0 + tig]);
        a[1] = __float_as_uint(sP[(rowA + g + 8) * STRIDE + k0 + tig]);
        a[2] = __float_as_uint(sP[(rowA + g)     * STRIDE + k0 + tig + 4]);
        a[3] = __float_as_uint(sP[(rowA + g + 8) * STRIDE + k0 + tig + 4]);
        #pragma unroll
        for (int nt = 0; nt < 8; ++nt) {
            uint32_t b[2];
            b[0] = __float_as_uint(sK[(nt * 8 + g) * STRIDE + k0 + tig]);
            b[1] = __float_as_uint(sK[(nt * 8 + g) * STRIDE + k0 + tig + 4]);
            mma_tf32(acc[nt], a, b);
        }
    }

    // ---------------- epilogue: out[b] = sum_o t[b][o] * q[b][o] ----------------
    // c0: (row g,  col nt*8+2*tig), c1: col+1; c2/c3: row g+8
    float s0 = 0.0f, s1 = 0.0f;
    #pragma unroll
    for (int nt = 0; nt < 8; ++nt) {
        const int col = nt * 8 + tig * 2;
        float2 q0 = *(const float2*)&sQ[(rowA + g)     * STRIDE + col];
        float2 q1 = *(const float2*)&sQ[(rowA + g + 8) * STRIDE + col];
        s0 = fmaf(acc[nt][0], q0.x, fmaf(acc[nt][1], q0.y, s0));
        s1 = fmaf(acc[nt][2], q1.x, fmaf(acc[nt][3], q1.y, s1));
    }
    s0 += __shfl_xor_sync(0xFFFFFFFFu, s0, 1, 4);
    s0 += __shfl_xor_sync(0xFFFFFFFFu, s0, 2, 4);
    s1 += __shfl_xor_sync(0xFFFFFFFFu, s1, 1, 4);
    s1 += __shfl_xor_sync(0xFFFFFFFFu, s1, 2, 4);
    if (tig == 0) {
        out[(size_t)(b0 + rowA + g)     * NIX + n] = s0;
        out[(size_t)(b0 + rowA + g + 8) * NIX + n] = s1;
    }
}

extern "C" void kernel_launch(void* const* d_in, const int* in_sizes, int n_in,
                              void* d_out, int out_size)
{
    (void)in_sizes; (void)n_in; (void)out_size;
    const float* x    = (const float*)d_in[0];   // (8192, 32, 64) f32
    const float* kern = (const float*)d_in[1];   // (64, 496, 64) f32
    float* out        = (float*)d_out;           // (8192, 496) f32

    const int smem_bytes = SMEM_FLOATS * (int)sizeof(float);   // 87040
    cudaFuncSetAttribute(opn_mma_kernel, cudaFuncAttributeMaxDynamicSharedMemorySize, smem_bytes);

    dim3 grid(NIX, B_TOT / BT);   // (496, 64)
    opn_mma_kernel<<<grid, NTHREADS, smem_bytes>>>(x, kern, out);
}

// round 4
// speedup vs baseline: 2.5045x; 1.2071x over previous
#include <cuda_runtime.h>
#include <cstdint>

#define B_TOT   8192
#define NF      32
#define D       64
#define NIX     496
#define BT      128
#define NTHREADS 128      // 4 warps
#define STRIDE  68        // padded row stride (floats), conflict-free

// smem (floats): sP[128][68], sK[64][68]   (no sQ -> 4 CTAs/SM)
#define SP_F (BT * STRIDE)
#define SK_F (64 * STRIDE)
#define SMEM_FLOATS (SP_F + SK_F)

__device__ __forceinline__ float f2tf32(float f) {
    uint32_t r; asm("cvt.rn.tf32.f32 %0, %1;" : "=r"(r) : "f"(f));
    return __uint_as_float(r);
}
__device__ __forceinline__ void mma_tf32(float d[4], const uint32_t a[4], const uint32_t b[2]) {
    asm volatile(
        "mma.sync.aligned.m16n8k8.row.col.f32.tf32.tf32.f32 "
        "{%0,%1,%2,%3}, {%4,%5,%6,%7}, {%8,%9}, {%0,%1,%2,%3};"
        : "+f"(d[0]), "+f"(d[1]), "+f"(d[2]), "+f"(d[3])
        : "r"(a[0]), "r"(a[1]), "r"(a[2]), "r"(a[3]), "r"(b[0]), "r"(b[1]));
}

extern "C" __global__ void __launch_bounds__(NTHREADS, 4)
opn_mma4_kernel(const float* __restrict__ x,
                const float* __restrict__ kern,
                float* __restrict__ out)
{
    const int n    = blockIdx.x;
    const int bblk = blockIdx.y;
    const int tid  = threadIdx.x;
    const int wid  = tid >> 5;
    const int lane = tid & 31;
    const int b0   = bblk * BT;

    // decode triu pair (r, c)
    int r = 0, nn = n;
    while (nn >= (NF - 1 - r)) { nn -= (NF - 1 - r); r++; }
    const int c = r + 1 + nn;

    extern __shared__ float smem[];
    float* sP = smem;
    float* sK = sP + SP_F;

    // ---------------- loads: P and K -> tf32 in smem ----------------
    {
        const int f4 = tid & 15;     // 16B chunk within a 64-float row
        const int rb = tid >> 4;     // 0..7

        const float4* xp4 = (const float4*)(x + ((size_t)b0 * NF + r) * D);
        #pragma unroll
        for (int pass = 0; pass < 16; ++pass) {
            int b = rb + pass * 8;
            float4 v = __ldg(xp4 + (size_t)b * (NF * D / 4) + f4);
            float4 t = { f2tf32(v.x), f2tf32(v.y), f2tf32(v.z), f2tf32(v.w) };
            *(float4*)&sP[b * STRIDE + f4 * 4] = t;
        }
        #pragma unroll
        for (int pass = 0; pass < 8; ++pass) {
            int o = rb + pass * 8;
            const float4* kp4 = (const float4*)(kern + ((size_t)o * NIX + n) * D);
            float4 v = __ldg(kp4 + f4);
            float4 t = { f2tf32(v.x), f2tf32(v.y), f2tf32(v.z), f2tf32(v.w) };
            *(float4*)&sK[o * STRIDE + f4 * 4] = t;
        }
    }
    __syncthreads();

    // ---------------- MMA main loop ----------------
    // Warp wid owns M rows [wid*32, wid*32+32): m-tiles mt=0,1. Full N=64 (nt=0..7), K=64.
    const int g    = lane >> 2;   // 0..7
    const int tig  = lane & 3;    // 0..3
    const int rowW = wid * 32;

    float acc[2][8][4];
    #pragma unroll
    for (int mt = 0; mt < 2; ++mt)
        #pragma unroll
        for (int t = 0; t < 8; ++t)
            #pragma unroll
            for (int j = 0; j < 4; ++j) acc[mt][t][j] = 0.0f;

    #pragma unroll
    for (int ks = 0; ks < 8; ++ks) {
        const int k0 = ks * 8;
        uint32_t a[2][4];
        #pragma unroll
        for (int mt = 0; mt < 2; ++mt) {
            const int rowA = rowW + mt * 16;
            a[mt][0] = __float_as_uint(sP[(rowA + g)     * STRIDE + k0 + tig]);
            a[mt][1] = __float_as_uint(sP[(rowA + g + 8) * STRIDE + k0 + tig]);
            a[mt][2] = __float_as_uint(sP[(rowA + g)     * STRIDE + k0 + tig + 4]);
            a[mt][3] = __float_as_uint(sP[(rowA + g + 8) * STRIDE + k0 + tig + 4]);
        }
        #pragma unroll
        for (int nt = 0; nt < 8; ++nt) {
            uint32_t b[2];
            b[0] = __float_as_uint(sK[(nt * 8 + g) * STRIDE + k0 + tig]);
            b[1] = __float_as_uint(sK[(nt * 8 + g) * STRIDE + k0 + tig + 4]);
            mma_tf32(acc[0][nt], a[0], b);
            mma_tf32(acc[1][nt], a[1], b);
        }
    }

    // ---------------- epilogue: out[b] = sum_o t[b][o] * q[b][o], q from gmem ----------------
    // acc[mt][nt]: c0=(row rowW+mt*16+g, col nt*8+tig*2), c1=col+1, c2/c3: row +8
    #pragma unroll
    for (int mt = 0; mt < 2; ++mt) {
        const int row0 = rowW + mt * 16 + g;
        const float* q0p = x + ((size_t)(b0 + row0)     * NF + c) * D;
        const float* q1p = x + ((size_t)(b0 + row0 + 8) * NF + c) * D;
        float s0 = 0.0f, s1 = 0.0f;
        #pragma unroll
        for (int nt = 0; nt < 8; ++nt) {
            const int col = nt * 8 + tig * 2;
            float2 q0 = __ldg((const float2*)(q0p + col));
            float2 q1 = __ldg((const float2*)(q1p + col));
            s0 = fmaf(acc[mt][nt][0], q0.x, fmaf(acc[mt][nt][1], q0.y, s0));
            s1 = fmaf(acc[mt][nt][2], q1.x, fmaf(acc[mt][nt][3], q1.y, s1));
        }
        s0 += __shfl_xor_sync(0xFFFFFFFFu, s0, 1, 4);
        s0 += __shfl_xor_sync(0xFFFFFFFFu, s0, 2, 4);
        s1 += __shfl_xor_sync(0xFFFFFFFFu, s1, 1, 4);
        s1 += __shfl_xor_sync(0xFFFFFFFFu, s1, 2, 4);
        if (tig == 0) {
            out[(size_t)(b0 + row0)     * NIX + n] = s0;
            out[(size_t)(b0 + row0 + 8) * NIX + n] = s1;
        }
    }
}

extern "C" void kernel_launch(void* const* d_in, const int* in_sizes, int n_in,
                              void* d_out, int out_size)
{
    (void)in_sizes; (void)n_in; (void)out_size;
    const float* x    = (const float*)d_in[0];   // (8192, 32, 64) f32
    const float* kern = (const float*)d_in[1];   // (64, 496, 64) f32
    float* out        = (float*)d_out;           // (8192, 496) f32

    const int smem_bytes = SMEM_FLOATS * (int)sizeof(float);   // 52224
    cudaFuncSetAttribute(opn_mma4_kernel, cudaFuncAttributeMaxDynamicSharedMemorySize, smem_bytes);

    dim3 grid(NIX, B_TOT / BT);   // (496, 64)
    opn_mma4_kernel<<<grid, NTHREADS, smem_bytes>>>(x, kern, out);
}

// round 6
// speedup vs baseline: 2.6683x; 1.0654x over previous
#include <cuda_runtime.h>
#include <cstdint>

#define B_TOT   8192
#define NF      32
#define D       64
#define NIX     496
#define BT      256       // batch rows per CTA
#define NTHREADS 128      // 4 warps, each owns M=64 rows, full N=64
#define STRIDE  68        // padded row stride (floats), conflict-free

// smem (floats): sP[256][68], sK[64][68]
#define SP_F (BT * STRIDE)
#define SK_F (64 * STRIDE)
#define SMEM_FLOATS (SP_F + SK_F)     // 87040 B

__device__ __forceinline__ float f2tf32(float f) {
    uint32_t r; asm("cvt.rn.tf32.f32 %0, %1;" : "=r"(r) : "f"(f));
    return __uint_as_float(r);
}
__device__ __forceinline__ void mma_tf32(float d[4], const uint32_t a[4], const uint32_t b[2]) {
    asm volatile(
        "mma.sync.aligned.m16n8k8.row.col.f32.tf32.tf32.f32 "
        "{%0,%1,%2,%3}, {%4,%5,%6,%7}, {%8,%9}, {%0,%1,%2,%3};"
        : "+f"(d[0]), "+f"(d[1]), "+f"(d[2]), "+f"(d[3])
        : "r"(a[0]), "r"(a[1]), "r"(a[2]), "r"(a[3]), "r"(b[0]), "r"(b[1]));
}

extern "C" __global__ void __launch_bounds__(NTHREADS, 2)
opn_mma5_kernel(const float* __restrict__ x,
                const float* __restrict__ kern,
                float* __restrict__ out)
{
    const int n    = blockIdx.x;
    const int bblk = blockIdx.y;
    const int tid  = threadIdx.x;
    const int wid  = tid >> 5;
    const int lane = tid & 31;
    const int b0   = bblk * BT;

    // decode triu pair (r, c)
    int r = 0, nn = n;
    while (nn >= (NF - 1 - r)) { nn -= (NF - 1 - r); r++; }
    const int c = r + 1 + nn;

    extern __shared__ float smem[];
    float* sP = smem;
    float* sK = sP + SP_F;

    // ---------------- loads: P and K -> tf32 in smem ----------------
    {
        const int f4 = tid & 15;     // 16B chunk within a 64-float row
        const int rb = tid >> 4;     // 0..7

        const float4* xp4 = (const float4*)(x + ((size_t)b0 * NF + r) * D);
        #pragma unroll
        for (int pass = 0; pass < 32; ++pass) {
            int b = rb + pass * 8;
            float4 v = __ldg(xp4 + (size_t)b * (NF * D / 4) + f4);
            float4 t = { f2tf32(v.x), f2tf32(v.y), f2tf32(v.z), f2tf32(v.w) };
            *(float4*)&sP[b * STRIDE + f4 * 4] = t;
        }
        #pragma unroll
        for (int pass = 0; pass < 8; ++pass) {
            int o = rb + pass * 8;
            const float4* kp4 = (const float4*)(kern + ((size_t)o * NIX + n) * D);
            float4 v = __ldg(kp4 + f4);
            float4 t = { f2tf32(v.x), f2tf32(v.y), f2tf32(v.z), f2tf32(v.w) };
            *(float4*)&sK[o * STRIDE + f4 * 4] = t;
        }
    }
    __syncthreads();

    // ---------------- MMA main loop ----------------
    // Warp wid owns M rows [wid*64, wid*64+64): m-tiles mt=0..3. Full N=64, K=64.
    const int g    = lane >> 2;   // 0..7
    const int tig  = lane & 3;    // 0..3
    const int rowW = wid * 64;

    float acc[4][8][4];
    #pragma unroll
    for (int mt = 0; mt < 4; ++mt)
        #pragma unroll
        for (int t = 0; t < 8; ++t)
            #pragma unroll
            for (int j = 0; j < 4; ++j) acc[mt][t][j] = 0.0f;

    #pragma unroll
    for (int ks = 0; ks < 8; ++ks) {
        const int k0 = ks * 8;
        uint32_t a[4][4];
        #pragma unroll
        for (int mt = 0; mt < 4; ++mt) {
            const int rowA = rowW + mt * 16;
            a[mt][0] = __float_as_uint(sP[(rowA + g)     * STRIDE + k0 + tig]);
            a[mt][1] = __float_as_uint(sP[(rowA + g + 8) * STRIDE + k0 + tig]);
            a[mt][2] = __float_as_uint(sP[(rowA + g)     * STRIDE + k0 + tig + 4]);
            a[mt][3] = __float_as_uint(sP[(rowA + g + 8) * STRIDE + k0 + tig + 4]);
        }
        #pragma unroll
        for (int nt = 0; nt < 8; ++nt) {
            uint32_t b[2];
            b[0] = __float_as_uint(sK[(nt * 8 + g) * STRIDE + k0 + tig]);
            b[1] = __float_as_uint(sK[(nt * 8 + g) * STRIDE + k0 + tig + 4]);
            #pragma unroll
            for (int mt = 0; mt < 4; ++mt)
                mma_tf32(acc[mt][nt], a[mt], b);
        }
    }

    // ---------------- epilogue: out[b] = sum_o t[b][o] * q[b][o], q from gmem ----------------
    #pragma unroll
    for (int mt = 0; mt < 4; ++mt) {
        const int row0 = rowW + mt * 16 + g;
        const float* q0p = x + ((size_t)(b0 + row0)     * NF + c) * D;
        const float* q1p = x + ((size_t)(b0 + row0 + 8) * NF + c) * D;
        float s0 = 0.0f, s1 = 0.0f;
        #pragma unroll
        for (int nt = 0; nt < 8; ++nt) {
            const int col = nt * 8 + tig * 2;
            float2 q0 = __ldg((const float2*)(q0p + col));
            float2 q1 = __ldg((const float2*)(q1p + col));
            s0 = fmaf(acc[mt][nt][0], q0.x, fmaf(acc[mt][nt][1], q0.y, s0));
            s1 = fmaf(acc[mt][nt][2], q1.x, fmaf(acc[mt][nt][3], q1.y, s1));
        }
        s0 += __shfl_xor_sync(0xFFFFFFFFu, s0, 1, 4);
        s0 += __shfl_xor_sync(0xFFFFFFFFu, s0, 2, 4);
        s1 += __shfl_xor_sync(0xFFFFFFFFu, s1, 1, 4);
        s1 += __shfl_xor_sync(0xFFFFFFFFu, s1, 2, 4);
        if (tig == 0) {
            out[(size_t)(b0 + row0)     * NIX + n] = s0;
            out[(size_t)(b0 + row0 + 8) * NIX + n] = s1;
        }
    }
}

extern "C" void kernel_launch(void* const* d_in, const int* in_sizes, int n_in,
                              void* d_out, int out_size)
{
    (void)in_sizes; (void)n_in; (void)out_size;
    const float* x    = (const float*)d_in[0];   // (8192, 32, 64) f32
    const float* kern = (const float*)d_in[1];   // (64, 496, 64) f32
    float* out        = (float*)d_out;           // (8192, 496) f32

    const int smem_bytes = SMEM_FLOATS * (int)sizeof(float);   // 87040
    cudaFuncSetAttribute(opn_mma5_kernel, cudaFuncAttributeMaxDynamicSharedMemorySize, smem_bytes);

    dim3 grid(NIX, B_TOT / BT);   // (496, 32)
    opn_mma5_kernel<<<grid, NTHREADS, smem_bytes>>>(x, kern, out);
}

// round 7
// speedup vs baseline: 3.2193x; 1.2065x over previous
#include <cuda_runtime.h>
#include <cstdint>

#define B_TOT   8192
#define NF      32
#define D       64
#define NIX     496
#define BT      256       // batch rows per CTA
#define NTHREADS 128      // 4 warps, each owns M=64 rows, full N=64
#define STRIDE  68        // padded row stride (floats), conflict-free
#define NGRP    136       // sum over r of ceil((31-r)/4)
#define PAIRS_PER_CTA 4

// smem (floats): sP[256][68], sK[64][68] (sK reloaded per pair)
#define SP_F (BT * STRIDE)
#define SK_F (64 * STRIDE)
#define SMEM_FLOATS (SP_F + SK_F)     // 87040 B

__device__ __forceinline__ float f2tf32(float f) {
    uint32_t r; asm("cvt.rn.tf32.f32 %0, %1;" : "=r"(r) : "f"(f));
    return __uint_as_float(r);
}
__device__ __forceinline__ void mma_tf32(float d[4], const uint32_t a[4], const uint32_t b[2]) {
    asm volatile(
        "mma.sync.aligned.m16n8k8.row.col.f32.tf32.tf32.f32 "
        "{%0,%1,%2,%3}, {%4,%5,%6,%7}, {%8,%9}, {%0,%1,%2,%3};"
        : "+f"(d[0]), "+f"(d[1]), "+f"(d[2]), "+f"(d[3])
        : "r"(a[0]), "r"(a[1]), "r"(a[2]), "r"(a[3]), "r"(b[0]), "r"(b[1]));
}

extern "C" __global__ void __launch_bounds__(NTHREADS, 2)
opn_mma7_kernel(const float* __restrict__ x,
                const float* __restrict__ kern,
                float* __restrict__ out)
{
    const int gx   = blockIdx.x;      // pair-group 0..135
    const int bblk = blockIdx.y;
    const int tid  = threadIdx.x;
    const int wid  = tid >> 5;
    const int lane = tid & 31;
    const int b0   = bblk * BT;

    // decode group -> (r, j): groups per r = ceil((31-r)/4) = (34-r)>>2
    int r = 0, g2 = gx;
    while (g2 >= ((34 - r) >> 2)) { g2 -= (34 - r) >> 2; r++; }
    const int cbase = r + 1 + 4 * g2;              // first c of this group
    const int nbase = r * 31 - (r * (r - 1)) / 2;  // n index of pair (r, r+1)

    extern __shared__ float smem[];
    float* sP = smem;
    float* sK = sP + SP_F;

    const int f4 = tid & 15;     // 16B chunk within a 64-float row
    const int rb = tid >> 4;     // 0..7

    // ---------------- P tile: loaded ONCE for all pairs in this group ----------------
    {
        const float4* xp4 = (const float4*)(x + ((size_t)b0 * NF + r) * D);
        #pragma unroll
        for (int pass = 0; pass < 32; ++pass) {
            int b = rb + pass * 8;
            float4 v = __ldg(xp4 + (size_t)b * (NF * D / 4) + f4);
            float4 t = { f2tf32(v.x), f2tf32(v.y), f2tf32(v.z), f2tf32(v.w) };
            *(float4*)&sP[b * STRIDE + f4 * 4] = t;
        }
    }

    const int g    = lane >> 2;   // 0..7
    const int tig  = lane & 3;    // 0..3
    const int rowW = wid * 64;

    for (int t = 0; t < PAIRS_PER_CTA; ++t) {
        const int c = cbase + t;
        if (c > 31) break;                 // uniform across CTA
        const int n = nbase + (c - r - 1);

        // ---- load K_n into sK (overwrites previous pair's) ----
        __syncthreads();                   // all warps done reading old sK / sP store done (t==0)
        #pragma unroll
        for (int pass = 0; pass < 8; ++pass) {
            int o = rb + pass * 8;
            const float4* kp4 = (const float4*)(kern + ((size_t)o * NIX + n) * D);
            float4 v = __ldg(kp4 + f4);
            float4 tt = { f2tf32(v.x), f2tf32(v.y), f2tf32(v.z), f2tf32(v.w) };
            *(float4*)&sK[o * STRIDE + f4 * 4] = tt;
        }
        __syncthreads();

        // ---- MMA main loop: warp owns M=64 rows, full N=64, K=64 ----
        float acc[4][8][4];
        #pragma unroll
        for (int mt = 0; mt < 4; ++mt)
            #pragma unroll
            for (int q = 0; q < 8; ++q)
                #pragma unroll
                for (int j = 0; j < 4; ++j) acc[mt][q][j] = 0.0f;

        #pragma unroll
        for (int ks = 0; ks < 8; ++ks) {
            const int k0 = ks * 8;
            uint32_t a[4][4];
            #pragma unroll
            for (int mt = 0; mt < 4; ++mt) {
                const int rowA = rowW + mt * 16;
                a[mt][0] = __float_as_uint(sP[(rowA + g)     * STRIDE + k0 + tig]);
                a[mt][1] = __float_as_uint(sP[(rowA + g + 8) * STRIDE + k0 + tig]);
                a[mt][2] = __float_as_uint(sP[(rowA + g)     * STRIDE + k0 + tig + 4]);
                a[mt][3] = __float_as_uint(sP[(rowA + g + 8) * STRIDE + k0 + tig + 4]);
            }
            #pragma unroll
            for (int nt = 0; nt < 8; ++nt) {
                uint32_t b[2];
                b[0] = __float_as_uint(sK[(nt * 8 + g) * STRIDE + k0 + tig]);
                b[1] = __float_as_uint(sK[(nt * 8 + g) * STRIDE + k0 + tig + 4]);
                #pragma unroll
                for (int mt = 0; mt < 4; ++mt)
                    mma_tf32(acc[mt][nt], a[mt], b);
            }
        }

        // ---- epilogue: out[b, n] = sum_o t[b][o] * x[b, c, o] ----
        #pragma unroll
        for (int mt = 0; mt < 4; ++mt) {
            const int row0 = rowW + mt * 16 + g;
            const float* q0p = x + ((size_t)(b0 + row0)     * NF + c) * D;
            const float* q1p = x + ((size_t)(b0 + row0 + 8) * NF + c) * D;
            float s0 = 0.0f, s1 = 0.0f;
            #pragma unroll
            for (int nt = 0; nt < 8; ++nt) {
                const int col = nt * 8 + tig * 2;
                float2 q0 = __ldg((const float2*)(q0p + col));
                float2 q1 = __ldg((const float2*)(q1p + col));
                s0 = fmaf(acc[mt][nt][0], q0.x, fmaf(acc[mt][nt][1], q0.y, s0));
                s1 = fmaf(acc[mt][nt][2], q1.x, fmaf(acc[mt][nt][3], q1.y, s1));
            }
            s0 += __shfl_xor_sync(0xFFFFFFFFu, s0, 1, 4);
            s0 += __shfl_xor_sync(0xFFFFFFFFu, s0, 2, 4);
            s1 += __shfl_xor_sync(0xFFFFFFFFu, s1, 1, 4);
            s1 += __shfl_xor_sync(0xFFFFFFFFu, s1, 2, 4);
            if (tig == 0) {
                out[(size_t)(b0 + row0)     * NIX + n] = s0;
                out[(size_t)(b0 + row0 + 8) * NIX + n] = s1;
            }
        }
    }
}

extern "C" void kernel_launch(void* const* d_in, const int* in_sizes, int n_in,
                              void* d_out, int out_size)
{
    (void)in_sizes; (void)n_in; (void)out_size;
    const float* x    = (const float*)d_in[0];   // (8192, 32, 64) f32
    const float* kern = (const float*)d_in[1];   // (64, 496, 64) f32
    float* out        = (float*)d_out;           // (8192, 496) f32

    const int smem_bytes = SMEM_FLOATS * (int)sizeof(float);   // 87040
    cudaFuncSetAttribute(opn_mma7_kernel, cudaFuncAttributeMaxDynamicSharedMemorySize, smem_bytes);

    dim3 grid(NGRP, B_TOT / BT);   // (136, 32)
    opn_mma7_kernel<<<grid, NTHREADS, smem_bytes>>>(x, kern, out);
}